// round 1
// baseline (speedup 1.0000x reference)
#include <cuda_runtime.h>
#include <math.h>

#define TT   2048
#define HID  2048
#define NH   16
#define NKV  8
#define HD   128
#define QS   (NH * HD)          // 2048
#define KVS  (NKV * HD)         // 1024
#define QKVN (QS + 2 * KVS)     // 4096

// Scratch (allocation-free rule: __device__ globals)
__device__ float g_qkv[TT * QKVN];   // 32 MB
__device__ float g_q[TT * NH * HD];  // 16 MB (normed+roped Q)
__device__ float g_k[TT * NKV * HD]; //  8 MB (normed+roped K)
__device__ float g_ctx[TT * QS];     // 16 MB

// ============================================================
// SGEMM (NT): C[M,N] = A[M,K] * B[N,K]^T, all row-major fp32.
// BM=BN=128, BK=8, 256 threads, 8x8 per-thread microtile.
// ============================================================
__global__ __launch_bounds__(256) void sgemm_nt(
    const float* __restrict__ A, const float* __restrict__ B,
    float* __restrict__ C, int M, int N, int K)
{
    __shared__ float As[8][128];
    __shared__ float Bs[8][128];
    const int bm = blockIdx.y * 128;
    const int bn = blockIdx.x * 128;
    const int tid = threadIdx.x;
    const int tm = (tid >> 4) << 3;   // 0..120
    const int tn = (tid & 15) << 3;   // 0..120
    const int lr = tid >> 1;          // 0..127
    const int lc = (tid & 1) << 2;    // 0 or 4

    const float* Ag = A + (size_t)(bm + lr) * K + lc;
    const float* Bg = B + (size_t)(bn + lr) * K + lc;

    float acc[8][8];
#pragma unroll
    for (int i = 0; i < 8; i++)
#pragma unroll
        for (int j = 0; j < 8; j++) acc[i][j] = 0.f;

    for (int k0 = 0; k0 < K; k0 += 8) {
        float4 a4 = *(const float4*)(Ag + k0);
        float4 b4 = *(const float4*)(Bg + k0);
        As[lc + 0][lr] = a4.x; As[lc + 1][lr] = a4.y;
        As[lc + 2][lr] = a4.z; As[lc + 3][lr] = a4.w;
        Bs[lc + 0][lr] = b4.x; Bs[lc + 1][lr] = b4.y;
        Bs[lc + 2][lr] = b4.z; Bs[lc + 3][lr] = b4.w;
        __syncthreads();
#pragma unroll
        for (int kk = 0; kk < 8; kk++) {
            float ra[8], rb[8];
            *(float4*)&ra[0] = *(const float4*)&As[kk][tm];
            *(float4*)&ra[4] = *(const float4*)&As[kk][tm + 4];
            *(float4*)&rb[0] = *(const float4*)&Bs[kk][tn];
            *(float4*)&rb[4] = *(const float4*)&Bs[kk][tn + 4];
#pragma unroll
            for (int i = 0; i < 8; i++)
#pragma unroll
                for (int j = 0; j < 8; j++)
                    acc[i][j] = fmaf(ra[i], rb[j], acc[i][j]);
        }
        __syncthreads();
    }
#pragma unroll
    for (int i = 0; i < 8; i++) {
        float* Cp = C + (size_t)(bm + tm + i) * N + bn + tn;
        *(float4*)Cp       = make_float4(acc[i][0], acc[i][1], acc[i][2], acc[i][3]);
        *(float4*)(Cp + 4) = make_float4(acc[i][4], acc[i][5], acc[i][6], acc[i][7]);
    }
}

// ============================================================
// Per-head RMSNorm + RoPE for Q (16 heads) and K (8 heads).
// grid (T, 24), block 128 (one thread per dim element).
// ============================================================
__global__ __launch_bounds__(128) void norm_rope_kernel(
    const float* __restrict__ qkv, const int* __restrict__ pos,
    const float* __restrict__ qw,  const float* __restrict__ kw,
    float* __restrict__ qout, float* __restrict__ kout)
{
    const int t  = blockIdx.x;
    const int hh = blockIdx.y;   // 0..15 => Q head, 16..23 => K head
    const int d  = threadIdx.x;  // 0..127

    const float* src; const float* w; float* dst;
    if (hh < NH) {
        src = qkv + (size_t)t * QKVN + hh * HD;
        w = qw;
        dst = qout + ((size_t)t * NH + hh) * HD;
    } else {
        int kh = hh - NH;
        src = qkv + (size_t)t * QKVN + QS + kh * HD;
        w = kw;
        dst = kout + ((size_t)t * NKV + kh) * HD;
    }

    float x = src[d];
    float ss = x * x;
#pragma unroll
    for (int o = 16; o > 0; o >>= 1)
        ss += __shfl_xor_sync(0xffffffffu, ss, o);

    __shared__ float red[4];
    __shared__ float xs[128];
    if ((d & 31) == 0) red[d >> 5] = ss;
    __syncthreads();
    float ms = (red[0] + red[1] + red[2] + red[3]) * (1.f / 128.f);
    float xn = x * rsqrtf(ms + 1e-6f) * w[d];
    xs[d] = xn;
    __syncthreads();

    float p = (float)pos[t];
    int i = d & 63;
    // inv_freq = 10000^(-i/64) = 2^(-i * log2(10000)/64)
    float freq = p * exp2f((float)i * -0.2076205059304601f);
    float s, c;
    sincosf(freq, &s, &c);  // accurate version (args up to ~2047)
    float other = (d < 64) ? xs[d + 64] : xs[d - 64];
    dst[d] = (d < 64) ? (xn * c - other * s) : (xn * c + other * s);
}

// ============================================================
// Causal flash attention (fp32, online softmax).
// Block: (q-tile of 64 rows, one Q head). 256 threads.
// Thread owns rows {rg, rg+32}, score cols {sw+8j}, output dims
// {32k + 4*sw + j}. All smem strides chosen bank-conflict-free.
// ============================================================
#define SQ_STR 132
#define SK_STR 132
#define SV_STR 132
#define SS_STR 36

__global__ __launch_bounds__(256) void attn_kernel(
    const float* __restrict__ Qb, const float* __restrict__ Kb,
    const float* __restrict__ QKV, float* __restrict__ ctx)
{
    extern __shared__ float sm[];
    float* sQ = sm;                      // 64 * 132
    float* sK = sQ + 64 * SQ_STR;        // 32 * 132
    float* sV = sK + 32 * SK_STR;        // 32 * 132
    float* sS = sV + 32 * SV_STR;        // 64 * 36

    const int h   = blockIdx.y;
    const int kvh = h >> 1;              // GQA: G = 2
    const int q0  = blockIdx.x * 64;
    const int tid = threadIdx.x;
    const int rg  = tid >> 3;            // 0..31
    const int sw  = tid & 7;             // 0..7
    const int ra  = rg;
    const int rb  = rg + 32;
    const float scale = 0.088388347648318447f;  // 128^-0.5

    // Load Q tile (64 x 128)
#pragma unroll
    for (int i = 0; i < 8; i++) {
        int e = tid + i * 256;
        int qr = e >> 5;
        int c = (e & 31) << 2;
        float4 v = *(const float4*)(Qb + (size_t)(q0 + qr) * QS + h * HD + c);
        *(float4*)(sQ + qr * SQ_STR + c) = v;
    }

    float4 acca[4], accb[4];
#pragma unroll
    for (int k = 0; k < 4; k++) {
        acca[k] = make_float4(0.f, 0.f, 0.f, 0.f);
        accb[k] = make_float4(0.f, 0.f, 0.f, 0.f);
    }
    float ma = -INFINITY, la = 0.f;
    float mb = -INFINITY, lb = 0.f;

    const int nt = (q0 >> 5) + 2;  // kv tiles of 32 needed (causal)
    for (int t0 = 0; t0 < nt; t0++) {
        const int s0 = t0 << 5;
        __syncthreads();
        // Load K and V tiles (32 x 128 each)
#pragma unroll
        for (int i = 0; i < 4; i++) {
            int e = tid + i * 256;
            int sr = e >> 5;
            int c = (e & 31) << 2;
            float4 k4 = *(const float4*)(Kb + (size_t)(s0 + sr) * KVS + kvh * HD + c);
            *(float4*)(sK + sr * SK_STR + c) = k4;
            float4 v4 = *(const float4*)(QKV + (size_t)(s0 + sr) * QKVN + (QS + KVS) + kvh * HD + c);
            *(float4*)(sV + sr * SV_STR + c) = v4;
        }
        __syncthreads();

        // Scores: 2 rows x 4 s-columns per thread
        float sca[4] = {0.f, 0.f, 0.f, 0.f};
        float scb[4] = {0.f, 0.f, 0.f, 0.f};
#pragma unroll 4
        for (int c = 0; c < 128; c += 4) {
            float4 qa = *(const float4*)(sQ + ra * SQ_STR + c);
            float4 qb = *(const float4*)(sQ + rb * SQ_STR + c);
#pragma unroll
            for (int j = 0; j < 4; j++) {
                float4 k4 = *(const float4*)(sK + (sw + 8 * j) * SK_STR + c);
                sca[j] += qa.x * k4.x + qa.y * k4.y + qa.z * k4.z + qa.w * k4.w;
                scb[j] += qb.x * k4.x + qb.y * k4.y + qb.z * k4.z + qb.w * k4.w;
            }
        }

        // Online softmax — row a
        {
            int qi = q0 + ra;
            float mt = -INFINITY;
#pragma unroll
            for (int j = 0; j < 4; j++) {
                int si = s0 + sw + 8 * j;
                sca[j] = (si <= qi) ? sca[j] * scale : -INFINITY;
                mt = fmaxf(mt, sca[j]);
            }
            mt = fmaxf(mt, __shfl_xor_sync(0xffffffffu, mt, 1));
            mt = fmaxf(mt, __shfl_xor_sync(0xffffffffu, mt, 2));
            mt = fmaxf(mt, __shfl_xor_sync(0xffffffffu, mt, 4));
            float mn = fmaxf(ma, mt);
            float lt = 0.f;
#pragma unroll
            for (int j = 0; j < 4; j++) {
                float p = __expf(sca[j] - mn);
                lt += p;
                sS[ra * SS_STR + sw + 8 * j] = p;
            }
            lt += __shfl_xor_sync(0xffffffffu, lt, 1);
            lt += __shfl_xor_sync(0xffffffffu, lt, 2);
            lt += __shfl_xor_sync(0xffffffffu, lt, 4);
            float f = __expf(ma - mn);
#pragma unroll
            for (int k = 0; k < 4; k++) {
                acca[k].x *= f; acca[k].y *= f; acca[k].z *= f; acca[k].w *= f;
            }
            la = la * f + lt;
            ma = mn;
        }
        // Online softmax — row b
        {
            int qi = q0 + rb;
            float mt = -INFINITY;
#pragma unroll
            for (int j = 0; j < 4; j++) {
                int si = s0 + sw + 8 * j;
                scb[j] = (si <= qi) ? scb[j] * scale : -INFINITY;
                mt = fmaxf(mt, scb[j]);
            }
            mt = fmaxf(mt, __shfl_xor_sync(0xffffffffu, mt, 1));
            mt = fmaxf(mt, __shfl_xor_sync(0xffffffffu, mt, 2));
            mt = fmaxf(mt, __shfl_xor_sync(0xffffffffu, mt, 4));
            float mn = fmaxf(mb, mt);
            float lt = 0.f;
#pragma unroll
            for (int j = 0; j < 4; j++) {
                float p = __expf(scb[j] - mn);
                lt += p;
                sS[rb * SS_STR + sw + 8 * j] = p;
            }
            lt += __shfl_xor_sync(0xffffffffu, lt, 1);
            lt += __shfl_xor_sync(0xffffffffu, lt, 2);
            lt += __shfl_xor_sync(0xffffffffu, lt, 4);
            float f = __expf(mb - mn);
#pragma unroll
            for (int k = 0; k < 4; k++) {
                accb[k].x *= f; accb[k].y *= f; accb[k].z *= f; accb[k].w *= f;
            }
            lb = lb * f + lt;
            mb = mn;
        }
        __syncwarp();  // p-values visible within the 8-lane row groups

        // PV accumulate
        for (int s4 = 0; s4 < 32; s4 += 4) {
            float4 pa4 = *(const float4*)(sS + ra * SS_STR + s4);
            float4 pb4 = *(const float4*)(sS + rb * SS_STR + s4);
            float pav[4] = {pa4.x, pa4.y, pa4.z, pa4.w};
            float pbv[4] = {pb4.x, pb4.y, pb4.z, pb4.w};
#pragma unroll
            for (int cc = 0; cc < 4; cc++) {
#pragma unroll
                for (int k = 0; k < 4; k++) {
                    float4 v4 = *(const float4*)(sV + (s4 + cc) * SV_STR + 32 * k + 4 * sw);
                    acca[k].x = fmaf(pav[cc], v4.x, acca[k].x);
                    acca[k].y = fmaf(pav[cc], v4.y, acca[k].y);
                    acca[k].z = fmaf(pav[cc], v4.z, acca[k].z);
                    acca[k].w = fmaf(pav[cc], v4.w, acca[k].w);
                    accb[k].x = fmaf(pbv[cc], v4.x, accb[k].x);
                    accb[k].y = fmaf(pbv[cc], v4.y, accb[k].y);
                    accb[k].z = fmaf(pbv[cc], v4.z, accb[k].z);
                    accb[k].w = fmaf(pbv[cc], v4.w, accb[k].w);
                }
            }
        }
    }

    float ila = 1.f / la;
    float ilb = 1.f / lb;
#pragma unroll
    for (int k = 0; k < 4; k++) {
        float4 oa = make_float4(acca[k].x * ila, acca[k].y * ila,
                                acca[k].z * ila, acca[k].w * ila);
        float4 ob = make_float4(accb[k].x * ilb, accb[k].y * ilb,
                                accb[k].z * ilb, accb[k].w * ilb);
        *(float4*)(ctx + (size_t)(q0 + ra) * QS + h * HD + 32 * k + 4 * sw) = oa;
        *(float4*)(ctx + (size_t)(q0 + rb) * QS + h * HD + 32 * k + 4 * sw) = ob;
    }
}

// ============================================================
extern "C" void kernel_launch(void* const* d_in, const int* in_sizes, int n_in,
                              void* d_out, int out_size)
{
    const int*   positions = (const int*)d_in[0];
    const float* hidden    = (const float*)d_in[1];
    const float* qkv_w     = (const float*)d_in[2];
    const float* q_norm_w  = (const float*)d_in[3];
    const float* k_norm_w  = (const float*)d_in[4];
    const float* o_w       = (const float*)d_in[5];
    float* out = (float*)d_out;

    float *qkv, *qb, *kb, *ctx;
    cudaGetSymbolAddress((void**)&qkv, g_qkv);
    cudaGetSymbolAddress((void**)&qb,  g_q);
    cudaGetSymbolAddress((void**)&kb,  g_k);
    cudaGetSymbolAddress((void**)&ctx, g_ctx);

    // 1) QKV projection: [2048,2048] @ [4096,2048]^T -> [2048,4096]
    sgemm_nt<<<dim3(QKVN / 128, TT / 128), 256>>>(hidden, qkv_w, qkv, TT, QKVN, HID);

    // 2) RMSNorm + RoPE on Q and K heads
    norm_rope_kernel<<<dim3(TT, NH + NKV), 128>>>(qkv, positions, q_norm_w, k_norm_w, qb, kb);

    // 3) Causal GQA flash attention
    const int smem = (64 * SQ_STR + 32 * SK_STR + 32 * SV_STR + 64 * SS_STR) * (int)sizeof(float);
    cudaFuncSetAttribute(attn_kernel, cudaFuncAttributeMaxDynamicSharedMemorySize, smem);
    attn_kernel<<<dim3(TT / 64, NH), 256, smem>>>(qb, kb, qkv, ctx);

    // 4) Output projection: [2048,2048] @ [2048,2048]^T -> [2048,2048]
    sgemm_nt<<<dim3(HID / 128, TT / 128), 256>>>(ctx, o_w, out, TT, HID, QS);
}

// round 3
// speedup vs baseline: 1.6335x; 1.6335x over previous
#include <cuda_runtime.h>
#include <cuda_bf16.h>
#include <math.h>
#include <cstdint>

#define TT   2048
#define HID  2048
#define NH   16
#define NKV  8
#define HD   128
#define QS   (NH * HD)          // 2048
#define KVS  (NKV * HD)         // 1024
#define QKVN (QS + 2 * KVS)     // 4096

// ---------------- scratch (__device__ globals; allocation-free rule) --------
__device__ float g_qkv[TT * QKVN];            // 32 MB
__device__ float g_q[TT * NH * HD];           // 16 MB
__device__ float g_k[TT * NKV * HD];          //  8 MB
__device__ float g_ctx[TT * QS];              // 16 MB
__device__ __nv_bfloat16 g_hid_h[TT * HID];
__device__ __nv_bfloat16 g_hid_l[TT * HID];
__device__ __nv_bfloat16 g_qkvw_h[QKVN * HID];
__device__ __nv_bfloat16 g_qkvw_l[QKVN * HID];
__device__ __nv_bfloat16 g_ow_h[HID * QS];
__device__ __nv_bfloat16 g_ow_l[HID * QS];
__device__ __nv_bfloat16 g_ctx_h[TT * QS];
__device__ __nv_bfloat16 g_ctx_l[TT * QS];

// ---------------- helpers -----------------------------------------------------
__device__ __forceinline__ uint32_t smem_u32(const void* p) {
    uint32_t a;
    asm("{ .reg .u64 t; cvta.to.shared.u64 t, %1; cvt.u32.u64 %0, t; }" : "=r"(a) : "l"(p));
    return a;
}

__device__ __forceinline__ void ldmx4(uint32_t* r, uint32_t addr) {
    asm volatile("ldmatrix.sync.aligned.m8n8.x4.shared.b16 {%0,%1,%2,%3}, [%4];"
                 : "=r"(r[0]), "=r"(r[1]), "=r"(r[2]), "=r"(r[3]) : "r"(addr));
}

__device__ __forceinline__ void mma16816(float* d, const uint32_t* a,
                                         uint32_t b0, uint32_t b1) {
    asm volatile(
        "mma.sync.aligned.m16n8k16.row.col.f32.bf16.bf16.f32 "
        "{%0,%1,%2,%3}, {%4,%5,%6,%7}, {%8,%9}, {%0,%1,%2,%3};"
        : "+f"(d[0]), "+f"(d[1]), "+f"(d[2]), "+f"(d[3])
        : "r"(a[0]), "r"(a[1]), "r"(a[2]), "r"(a[3]), "r"(b0), "r"(b1));
}

// ---------------- fp32 -> bf16 hi/lo split ------------------------------------
__global__ __launch_bounds__(256) void split_bf16(
    const float* __restrict__ x, __nv_bfloat16* __restrict__ h,
    __nv_bfloat16* __restrict__ l, int n4)
{
    int i = blockIdx.x * 256 + threadIdx.x;
    if (i >= n4) return;
    float4 v = ((const float4*)x)[i];
    __nv_bfloat16 h0 = __float2bfloat16_rn(v.x);
    __nv_bfloat16 h1 = __float2bfloat16_rn(v.y);
    __nv_bfloat16 h2 = __float2bfloat16_rn(v.z);
    __nv_bfloat16 h3 = __float2bfloat16_rn(v.w);
    __nv_bfloat16 l0 = __float2bfloat16_rn(v.x - __bfloat162float(h0));
    __nv_bfloat16 l1 = __float2bfloat16_rn(v.y - __bfloat162float(h1));
    __nv_bfloat16 l2 = __float2bfloat16_rn(v.z - __bfloat162float(h2));
    __nv_bfloat16 l3 = __float2bfloat16_rn(v.w - __bfloat162float(h3));
    ((ushort4*)h)[i] = make_ushort4(__bfloat16_as_ushort(h0), __bfloat16_as_ushort(h1),
                                    __bfloat16_as_ushort(h2), __bfloat16_as_ushort(h3));
    ((ushort4*)l)[i] = make_ushort4(__bfloat16_as_ushort(l0), __bfloat16_as_ushort(l1),
                                    __bfloat16_as_ushort(l2), __bfloat16_as_ushort(l3));
}

// ---------------- HMMA bf16x3 GEMM: C[M,N] = A[M,K] * B[N,K]^T (fp32) --------
// BM=128, BN=128, BK=32, 256 threads (8 warps, 4x2), warp tile 32x64.
// Smem tile row stride 80B: ldmatrix bank group = (5r + c) mod 8, conflict-free.
#define RSTR    80                       // bytes per smem row
#define TILE_B  (128 * RSTR)             // 10240
#define STAGE_B (4 * TILE_B)             // Ah, Al, Bh, Bl = 40960
#define DSMEM_B (2 * STAGE_B)            // 81920

__global__ __launch_bounds__(256) void gemm_mma(
    const __nv_bfloat16* __restrict__ Ah, const __nv_bfloat16* __restrict__ Al,
    const __nv_bfloat16* __restrict__ Bh, const __nv_bfloat16* __restrict__ Bl,
    float* __restrict__ C, int M, int N, int K)
{
    extern __shared__ char sal[];
    const int tid  = threadIdx.x;
    const int wid  = tid >> 5;
    const int lane = tid & 31;
    const int wm   = wid & 3;   // 0..3  (M warps)
    const int wn   = wid >> 2;  // 0..1  (N warps)
    const int bm = blockIdx.y * 128;
    const int bn = blockIdx.x * 128;
    const int NC = K >> 5;

    const uint32_t sb = smem_u32(sal);

    // loader geometry: thread -> rows {r0, r0+64}, 16B chunk c0
    const int r0 = tid >> 2;
    const int c0 = tid & 3;
    const size_t ga = (size_t)(bm + r0) * K + c0 * 8;
    const size_t gb = (size_t)(bn + r0) * K + c0 * 8;
    const uint32_t sofs = (uint32_t)(r0 * RSTR + c0 * 16);

    // ldmatrix per-thread address parts
    const uint32_t a_part = (uint32_t)((wm * 32 + (lane & 15)) * RSTR + (lane >> 4) * 16);
    const uint32_t b_part = (uint32_t)((wn * 64 + (lane & 7) + ((lane >> 4) << 3)) * RSTR
                                       + ((lane >> 3) & 1) * 16);

    float acc[2][8][4];
#pragma unroll
    for (int i = 0; i < 2; i++)
#pragma unroll
        for (int j = 0; j < 8; j++)
#pragma unroll
            for (int q = 0; q < 4; q++) acc[i][j][q] = 0.f;

    // prologue: stage 0
    {
        uint4 v0 = *(const uint4*)(Ah + ga);
        uint4 v1 = *(const uint4*)(Ah + ga + 64 * K);
        uint4 v2 = *(const uint4*)(Al + ga);
        uint4 v3 = *(const uint4*)(Al + ga + 64 * K);
        uint4 v4 = *(const uint4*)(Bh + gb);
        uint4 v5 = *(const uint4*)(Bh + gb + 64 * K);
        uint4 v6 = *(const uint4*)(Bl + gb);
        uint4 v7 = *(const uint4*)(Bl + gb + 64 * K);
        *(uint4*)(sal + 0 * TILE_B + sofs)             = v0;
        *(uint4*)(sal + 0 * TILE_B + sofs + 64 * RSTR) = v1;
        *(uint4*)(sal + 1 * TILE_B + sofs)             = v2;
        *(uint4*)(sal + 1 * TILE_B + sofs + 64 * RSTR) = v3;
        *(uint4*)(sal + 2 * TILE_B + sofs)             = v4;
        *(uint4*)(sal + 2 * TILE_B + sofs + 64 * RSTR) = v5;
        *(uint4*)(sal + 3 * TILE_B + sofs)             = v6;
        *(uint4*)(sal + 3 * TILE_B + sofs + 64 * RSTR) = v7;
    }
    __syncthreads();

    for (int c = 0; c < NC; c++) {
        const uint32_t so = (c & 1) ? STAGE_B : 0;
        uint4 v0, v1, v2, v3, v4, v5, v6, v7;
        const bool pre = (c + 1 < NC);
        if (pre) {
            const size_t k1 = (size_t)(c + 1) << 5;
            v0 = *(const uint4*)(Ah + ga + k1);
            v1 = *(const uint4*)(Ah + ga + k1 + 64 * K);
            v2 = *(const uint4*)(Al + ga + k1);
            v3 = *(const uint4*)(Al + ga + k1 + 64 * K);
            v4 = *(const uint4*)(Bh + gb + k1);
            v5 = *(const uint4*)(Bh + gb + k1 + 64 * K);
            v6 = *(const uint4*)(Bl + gb + k1);
            v7 = *(const uint4*)(Bl + gb + k1 + 64 * K);
        }

        const uint32_t sAh = sb + so + 0 * TILE_B;
        const uint32_t sAl = sb + so + 1 * TILE_B;
        const uint32_t sBh = sb + so + 2 * TILE_B;
        const uint32_t sBl = sb + so + 3 * TILE_B;

#pragma unroll
        for (int kk = 0; kk < 2; kk++) {
            uint32_t ah[2][4], al[2][4], bh[4][4], bl[4][4];
#pragma unroll
            for (int mt = 0; mt < 2; mt++) {
                ldmx4(ah[mt], sAh + a_part + mt * (16 * RSTR) + kk * 32);
                ldmx4(al[mt], sAl + a_part + mt * (16 * RSTR) + kk * 32);
            }
#pragma unroll
            for (int nt = 0; nt < 4; nt++) {
                ldmx4(bh[nt], sBh + b_part + nt * (16 * RSTR) + kk * 32);
                ldmx4(bl[nt], sBl + b_part + nt * (16 * RSTR) + kk * 32);
            }
#pragma unroll
            for (int mt = 0; mt < 2; mt++) {
#pragma unroll
                for (int nt = 0; nt < 4; nt++) {
                    mma16816(acc[mt][2 * nt],     ah[mt], bh[nt][0], bh[nt][1]);
                    mma16816(acc[mt][2 * nt],     ah[mt], bl[nt][0], bl[nt][1]);
                    mma16816(acc[mt][2 * nt],     al[mt], bh[nt][0], bh[nt][1]);
                    mma16816(acc[mt][2 * nt + 1], ah[mt], bh[nt][2], bh[nt][3]);
                    mma16816(acc[mt][2 * nt + 1], ah[mt], bl[nt][2], bl[nt][3]);
                    mma16816(acc[mt][2 * nt + 1], al[mt], bh[nt][2], bh[nt][3]);
                }
            }
        }

        if (pre) {
            const uint32_t so2 = so ^ STAGE_B;
            *(uint4*)(sal + so2 + 0 * TILE_B + sofs)             = v0;
            *(uint4*)(sal + so2 + 0 * TILE_B + sofs + 64 * RSTR) = v1;
            *(uint4*)(sal + so2 + 1 * TILE_B + sofs)             = v2;
            *(uint4*)(sal + so2 + 1 * TILE_B + sofs + 64 * RSTR) = v3;
            *(uint4*)(sal + so2 + 2 * TILE_B + sofs)             = v4;
            *(uint4*)(sal + so2 + 2 * TILE_B + sofs + 64 * RSTR) = v5;
            *(uint4*)(sal + so2 + 3 * TILE_B + sofs)             = v6;
            *(uint4*)(sal + so2 + 3 * TILE_B + sofs + 64 * RSTR) = v7;
        }
        __syncthreads();
    }

    // epilogue: fragment -> global fp32
    const int mr = bm + wm * 32 + (lane >> 2);
    const int nc0 = bn + wn * 64 + (lane & 3) * 2;
#pragma unroll
    for (int mt = 0; mt < 2; mt++) {
#pragma unroll
        for (int n8 = 0; n8 < 8; n8++) {
            int row = mr + mt * 16;
            int col = nc0 + n8 * 8;
            *(float2*)(C + (size_t)row * N + col) =
                make_float2(acc[mt][n8][0], acc[mt][n8][1]);
            *(float2*)(C + (size_t)(row + 8) * N + col) =
                make_float2(acc[mt][n8][2], acc[mt][n8][3]);
        }
    }
}

// ---------------- RMSNorm + RoPE ----------------------------------------------
__global__ __launch_bounds__(128) void norm_rope_kernel(
    const float* __restrict__ qkv, const int* __restrict__ pos,
    const float* __restrict__ qw,  const float* __restrict__ kw,
    float* __restrict__ qout, float* __restrict__ kout)
{
    const int t  = blockIdx.x;
    const int hh = blockIdx.y;
    const int d  = threadIdx.x;

    const float* src; const float* w; float* dst;
    if (hh < NH) {
        src = qkv + (size_t)t * QKVN + hh * HD;
        w = qw;
        dst = qout + ((size_t)t * NH + hh) * HD;
    } else {
        int kh = hh - NH;
        src = qkv + (size_t)t * QKVN + QS + kh * HD;
        w = kw;
        dst = kout + ((size_t)t * NKV + kh) * HD;
    }

    float x = src[d];
    float ss = x * x;
#pragma unroll
    for (int o = 16; o > 0; o >>= 1)
        ss += __shfl_xor_sync(0xffffffffu, ss, o);

    __shared__ float red[4];
    __shared__ float xs[128];
    if ((d & 31) == 0) red[d >> 5] = ss;
    __syncthreads();
    float ms = (red[0] + red[1] + red[2] + red[3]) * (1.f / 128.f);
    float xn = x * rsqrtf(ms + 1e-6f) * w[d];
    xs[d] = xn;
    __syncthreads();

    float p = (float)pos[t];
    int i = d & 63;
    float freq = p * exp2f((float)i * -0.2076205059304601f);
    float s, c;
    sincosf(freq, &s, &c);
    float other = (d < 64) ? xs[d + 64] : xs[d - 64];
    dst[d] = (d < 64) ? (xn * c - other * s) : (xn * c + other * s);
}

// ---------------- causal flash attention (unchanged, validated) ---------------
#define SQ_STR 132
#define SK_STR 132
#define SV_STR 132
#define SS_STR 36

__global__ __launch_bounds__(256) void attn_kernel(
    const float* __restrict__ Qb, const float* __restrict__ Kb,
    const float* __restrict__ QKV, float* __restrict__ ctx)
{
    extern __shared__ float sm[];
    float* sQ = sm;
    float* sK = sQ + 64 * SQ_STR;
    float* sV = sK + 32 * SK_STR;
    float* sS = sV + 32 * SV_STR;

    const int h   = blockIdx.y;
    const int kvh = h >> 1;
    const int q0  = blockIdx.x * 64;
    const int tid = threadIdx.x;
    const int rg  = tid >> 3;
    const int sw  = tid & 7;
    const int ra  = rg;
    const int rb  = rg + 32;
    const float scale = 0.088388347648318447f;

#pragma unroll
    for (int i = 0; i < 8; i++) {
        int e = tid + i * 256;
        int qr = e >> 5;
        int c = (e & 31) << 2;
        float4 v = *(const float4*)(Qb + (size_t)(q0 + qr) * QS + h * HD + c);
        *(float4*)(sQ + qr * SQ_STR + c) = v;
    }

    float4 acca[4], accb[4];
#pragma unroll
    for (int k = 0; k < 4; k++) {
        acca[k] = make_float4(0.f, 0.f, 0.f, 0.f);
        accb[k] = make_float4(0.f, 0.f, 0.f, 0.f);
    }
    float ma = -INFINITY, la = 0.f;
    float mb = -INFINITY, lb = 0.f;

    const int nt = (q0 >> 5) + 2;
    for (int t0 = 0; t0 < nt; t0++) {
        const int s0 = t0 << 5;
        __syncthreads();
#pragma unroll
        for (int i = 0; i < 4; i++) {
            int e = tid + i * 256;
            int sr = e >> 5;
            int c = (e & 31) << 2;
            float4 k4 = *(const float4*)(Kb + (size_t)(s0 + sr) * KVS + kvh * HD + c);
            *(float4*)(sK + sr * SK_STR + c) = k4;
            float4 v4 = *(const float4*)(QKV + (size_t)(s0 + sr) * QKVN + (QS + KVS) + kvh * HD + c);
            *(float4*)(sV + sr * SV_STR + c) = v4;
        }
        __syncthreads();

        float sca[4] = {0.f, 0.f, 0.f, 0.f};
        float scb[4] = {0.f, 0.f, 0.f, 0.f};
#pragma unroll 4
        for (int c = 0; c < 128; c += 4) {
            float4 qa = *(const float4*)(sQ + ra * SQ_STR + c);
            float4 qb = *(const float4*)(sQ + rb * SQ_STR + c);
#pragma unroll
            for (int j = 0; j < 4; j++) {
                float4 k4 = *(const float4*)(sK + (sw + 8 * j) * SK_STR + c);
                sca[j] += qa.x * k4.x + qa.y * k4.y + qa.z * k4.z + qa.w * k4.w;
                scb[j] += qb.x * k4.x + qb.y * k4.y + qb.z * k4.z + qb.w * k4.w;
            }
        }

        {
            int qi = q0 + ra;
            float mt = -INFINITY;
#pragma unroll
            for (int j = 0; j < 4; j++) {
                int si = s0 + sw + 8 * j;
                sca[j] = (si <= qi) ? sca[j] * scale : -INFINITY;
                mt = fmaxf(mt, sca[j]);
            }
            mt = fmaxf(mt, __shfl_xor_sync(0xffffffffu, mt, 1));
            mt = fmaxf(mt, __shfl_xor_sync(0xffffffffu, mt, 2));
            mt = fmaxf(mt, __shfl_xor_sync(0xffffffffu, mt, 4));
            float mn = fmaxf(ma, mt);
            float lt = 0.f;
#pragma unroll
            for (int j = 0; j < 4; j++) {
                float p = __expf(sca[j] - mn);
                lt += p;
                sS[ra * SS_STR + sw + 8 * j] = p;
            }
            lt += __shfl_xor_sync(0xffffffffu, lt, 1);
            lt += __shfl_xor_sync(0xffffffffu, lt, 2);
            lt += __shfl_xor_sync(0xffffffffu, lt, 4);
            float f = __expf(ma - mn);
#pragma unroll
            for (int k = 0; k < 4; k++) {
                acca[k].x *= f; acca[k].y *= f; acca[k].z *= f; acca[k].w *= f;
            }
            la = la * f + lt;
            ma = mn;
        }
        {
            int qi = q0 + rb;
            float mt = -INFINITY;
#pragma unroll
            for (int j = 0; j < 4; j++) {
                int si = s0 + sw + 8 * j;
                scb[j] = (si <= qi) ? scb[j] * scale : -INFINITY;
                mt = fmaxf(mt, scb[j]);
            }
            mt = fmaxf(mt, __shfl_xor_sync(0xffffffffu, mt, 1));
            mt = fmaxf(mt, __shfl_xor_sync(0xffffffffu, mt, 2));
            mt = fmaxf(mt, __shfl_xor_sync(0xffffffffu, mt, 4));
            float mn = fmaxf(mb, mt);
            float lt = 0.f;
#pragma unroll
            for (int j = 0; j < 4; j++) {
                float p = __expf(scb[j] - mn);
                lt += p;
                sS[rb * SS_STR + sw + 8 * j] = p;
            }
            lt += __shfl_xor_sync(0xffffffffu, lt, 1);
            lt += __shfl_xor_sync(0xffffffffu, lt, 2);
            lt += __shfl_xor_sync(0xffffffffu, lt, 4);
            float f = __expf(mb - mn);
#pragma unroll
            for (int k = 0; k < 4; k++) {
                accb[k].x *= f; accb[k].y *= f; accb[k].z *= f; accb[k].w *= f;
            }
            lb = lb * f + lt;
            mb = mn;
        }
        __syncwarp();

        for (int s4 = 0; s4 < 32; s4 += 4) {
            float4 pa4 = *(const float4*)(sS + ra * SS_STR + s4);
            float4 pb4 = *(const float4*)(sS + rb * SS_STR + s4);
            float pav[4] = {pa4.x, pa4.y, pa4.z, pa4.w};
            float pbv[4] = {pb4.x, pb4.y, pb4.z, pb4.w};
#pragma unroll
            for (int cc = 0; cc < 4; cc++) {
#pragma unroll
                for (int k = 0; k < 4; k++) {
                    float4 v4 = *(const float4*)(sV + (s4 + cc) * SV_STR + 32 * k + 4 * sw);
                    acca[k].x = fmaf(pav[cc], v4.x, acca[k].x);
                    acca[k].y = fmaf(pav[cc], v4.y, acca[k].y);
                    acca[k].z = fmaf(pav[cc], v4.z, acca[k].z);
                    acca[k].w = fmaf(pav[cc], v4.w, acca[k].w);
                    accb[k].x = fmaf(pbv[cc], v4.x, accb[k].x);
                    accb[k].y = fmaf(pbv[cc], v4.y, accb[k].y);
                    accb[k].z = fmaf(pbv[cc], v4.z, accb[k].z);
                    accb[k].w = fmaf(pbv[cc], v4.w, accb[k].w);
                }
            }
        }
    }

    float ila = 1.f / la;
    float ilb = 1.f / lb;
#pragma unroll
    for (int k = 0; k < 4; k++) {
        float4 oa = make_float4(acca[k].x * ila, acca[k].y * ila,
                                acca[k].z * ila, acca[k].w * ila);
        float4 ob = make_float4(accb[k].x * ilb, accb[k].y * ilb,
                                accb[k].z * ilb, accb[k].w * ilb);
        *(float4*)(ctx + (size_t)(q0 + ra) * QS + h * HD + 32 * k + 4 * sw) = oa;
        *(float4*)(ctx + (size_t)(q0 + rb) * QS + h * HD + 32 * k + 4 * sw) = ob;
    }
}

// ============================================================
extern "C" void kernel_launch(void* const* d_in, const int* in_sizes, int n_in,
                              void* d_out, int out_size)
{
    const int*   positions = (const int*)d_in[0];
    const float* hidden    = (const float*)d_in[1];
    const float* qkv_w     = (const float*)d_in[2];
    const float* q_norm_w  = (const float*)d_in[3];
    const float* k_norm_w  = (const float*)d_in[4];
    const float* o_w       = (const float*)d_in[5];
    float* out = (float*)d_out;

    float *qkv, *qb, *kb, *ctx;
    cudaGetSymbolAddress((void**)&qkv, g_qkv);
    cudaGetSymbolAddress((void**)&qb,  g_q);
    cudaGetSymbolAddress((void**)&kb,  g_k);
    cudaGetSymbolAddress((void**)&ctx, g_ctx);
    __nv_bfloat16 *hid_h, *hid_l, *qw_h, *qw_l, *ow_h, *ow_l, *cx_h, *cx_l;
    cudaGetSymbolAddress((void**)&hid_h, g_hid_h);
    cudaGetSymbolAddress((void**)&hid_l, g_hid_l);
    cudaGetSymbolAddress((void**)&qw_h,  g_qkvw_h);
    cudaGetSymbolAddress((void**)&qw_l,  g_qkvw_l);
    cudaGetSymbolAddress((void**)&ow_h,  g_ow_h);
    cudaGetSymbolAddress((void**)&ow_l,  g_ow_l);
    cudaGetSymbolAddress((void**)&cx_h,  g_ctx_h);
    cudaGetSymbolAddress((void**)&cx_l,  g_ctx_l);

    cudaFuncSetAttribute(gemm_mma, cudaFuncAttributeMaxDynamicSharedMemorySize, DSMEM_B);

    // 0) split fp32 operands into bf16 hi/lo
    split_bf16<<<(TT * HID / 4 + 255) / 256, 256>>>(hidden, hid_h, hid_l, TT * HID / 4);
    split_bf16<<<(QKVN * HID / 4 + 255) / 256, 256>>>(qkv_w, qw_h, qw_l, QKVN * HID / 4);
    split_bf16<<<(HID * QS / 4 + 255) / 256, 256>>>(o_w, ow_h, ow_l, HID * QS / 4);

    // 1) QKV projection (HMMA bf16x3)
    gemm_mma<<<dim3(QKVN / 128, TT / 128), 256, DSMEM_B>>>(
        hid_h, hid_l, qw_h, qw_l, qkv, TT, QKVN, HID);

    // 2) RMSNorm + RoPE
    norm_rope_kernel<<<dim3(TT, NH + NKV), 128>>>(qkv, positions, q_norm_w, k_norm_w, qb, kb);

    // 3) causal GQA flash attention
    const int smem = (64 * SQ_STR + 32 * SK_STR + 32 * SV_STR + 64 * SS_STR) * (int)sizeof(float);
    cudaFuncSetAttribute(attn_kernel, cudaFuncAttributeMaxDynamicSharedMemorySize, smem);
    attn_kernel<<<dim3(TT / 64, NH), 256, smem>>>(qb, kb, qkv, ctx);

    // 4) O projection (HMMA bf16x3)
    split_bf16<<<(TT * QS / 4 + 255) / 256, 256>>>(ctx, cx_h, cx_l, TT * QS / 4);
    gemm_mma<<<dim3(HID / 128, TT / 128), 256, DSMEM_B>>>(
        cx_h, cx_l, ow_h, ow_l, out, TT, HID, QS);
}

// round 4
// speedup vs baseline: 2.7145x; 1.6618x over previous
#include <cuda_runtime.h>
#include <cuda_bf16.h>
#include <math.h>
#include <cstdint>

#define TT   2048
#define HID  2048
#define NH   16
#define NKV  8
#define HD   128
#define QS   (NH * HD)          // 2048
#define KVS  (NKV * HD)         // 1024
#define QKVN (QS + 2 * KVS)     // 4096

// ---------------- scratch (__device__ globals; allocation-free rule) --------
__device__ float g_qkv[TT * QKVN];            // 32 MB
__device__ float g_ctx[TT * QS];              // 16 MB
__device__ __nv_bfloat16 g_hid_h[TT * HID];
__device__ __nv_bfloat16 g_hid_l[TT * HID];
__device__ __nv_bfloat16 g_qkvw_h[QKVN * HID];
__device__ __nv_bfloat16 g_qkvw_l[QKVN * HID];
__device__ __nv_bfloat16 g_ow_h[HID * QS];
__device__ __nv_bfloat16 g_ow_l[HID * QS];
__device__ __nv_bfloat16 g_ctx_h[TT * QS];
__device__ __nv_bfloat16 g_ctx_l[TT * QS];
__device__ __nv_bfloat16 g_qh[TT * QS];
__device__ __nv_bfloat16 g_ql[TT * QS];
__device__ __nv_bfloat16 g_kh[TT * KVS];
__device__ __nv_bfloat16 g_kl[TT * KVS];
__device__ __nv_bfloat16 g_vh[TT * KVS];
__device__ __nv_bfloat16 g_vl[TT * KVS];

// ---------------- helpers -----------------------------------------------------
__device__ __forceinline__ uint32_t smem_u32(const void* p) {
    uint32_t a;
    asm("{ .reg .u64 t; cvta.to.shared.u64 t, %1; cvt.u32.u64 %0, t; }" : "=r"(a) : "l"(p));
    return a;
}

__device__ __forceinline__ void ldmx4(uint32_t* r, uint32_t addr) {
    asm volatile("ldmatrix.sync.aligned.m8n8.x4.shared.b16 {%0,%1,%2,%3}, [%4];"
                 : "=r"(r[0]), "=r"(r[1]), "=r"(r[2]), "=r"(r[3]) : "r"(addr));
}
__device__ __forceinline__ void ldmx4t(uint32_t* r, uint32_t addr) {
    asm volatile("ldmatrix.sync.aligned.m8n8.x4.trans.shared.b16 {%0,%1,%2,%3}, [%4];"
                 : "=r"(r[0]), "=r"(r[1]), "=r"(r[2]), "=r"(r[3]) : "r"(addr));
}

__device__ __forceinline__ void mma16816(float* d, const uint32_t* a,
                                         uint32_t b0, uint32_t b1) {
    asm volatile(
        "mma.sync.aligned.m16n8k16.row.col.f32.bf16.bf16.f32 "
        "{%0,%1,%2,%3}, {%4,%5,%6,%7}, {%8,%9}, {%0,%1,%2,%3};"
        : "+f"(d[0]), "+f"(d[1]), "+f"(d[2]), "+f"(d[3])
        : "r"(a[0]), "r"(a[1]), "r"(a[2]), "r"(a[3]), "r"(b0), "r"(b1));
}

__device__ __forceinline__ uint32_t packbf(float lo, float hi) {
    uint32_t r;
    asm("cvt.rn.bf16x2.f32 %0, %1, %2;" : "=r"(r) : "f"(hi), "f"(lo));
    return r;
}

// ---------------- fp32 -> bf16 hi/lo split ------------------------------------
__global__ __launch_bounds__(256) void split_bf16(
    const float* __restrict__ x, __nv_bfloat16* __restrict__ h,
    __nv_bfloat16* __restrict__ l, int n4)
{
    int i = blockIdx.x * 256 + threadIdx.x;
    if (i >= n4) return;
    float4 v = ((const float4*)x)[i];
    __nv_bfloat16 h0 = __float2bfloat16_rn(v.x);
    __nv_bfloat16 h1 = __float2bfloat16_rn(v.y);
    __nv_bfloat16 h2 = __float2bfloat16_rn(v.z);
    __nv_bfloat16 h3 = __float2bfloat16_rn(v.w);
    __nv_bfloat16 l0 = __float2bfloat16_rn(v.x - __bfloat162float(h0));
    __nv_bfloat16 l1 = __float2bfloat16_rn(v.y - __bfloat162float(h1));
    __nv_bfloat16 l2 = __float2bfloat16_rn(v.z - __bfloat162float(h2));
    __nv_bfloat16 l3 = __float2bfloat16_rn(v.w - __bfloat162float(h3));
    ((ushort4*)h)[i] = make_ushort4(__bfloat16_as_ushort(h0), __bfloat16_as_ushort(h1),
                                    __bfloat16_as_ushort(h2), __bfloat16_as_ushort(h3));
    ((ushort4*)l)[i] = make_ushort4(__bfloat16_as_ushort(l0), __bfloat16_as_ushort(l1),
                                    __bfloat16_as_ushort(l2), __bfloat16_as_ushort(l3));
}

// ---------------- HMMA bf16x3 GEMM (unchanged, validated R3) ------------------
#define RSTR    80
#define TILE_B  (128 * RSTR)
#define STAGE_B (4 * TILE_B)
#define DSMEM_B (2 * STAGE_B)

__global__ __launch_bounds__(256) void gemm_mma(
    const __nv_bfloat16* __restrict__ Ah, const __nv_bfloat16* __restrict__ Al,
    const __nv_bfloat16* __restrict__ Bh, const __nv_bfloat16* __restrict__ Bl,
    float* __restrict__ C, int M, int N, int K)
{
    extern __shared__ char sal[];
    const int tid  = threadIdx.x;
    const int wid  = tid >> 5;
    const int lane = tid & 31;
    const int wm   = wid & 3;
    const int wn   = wid >> 2;
    const int bm = blockIdx.y * 128;
    const int bn = blockIdx.x * 128;
    const int NC = K >> 5;

    const uint32_t sb = smem_u32(sal);

    const int r0 = tid >> 2;
    const int c0 = tid & 3;
    const size_t ga = (size_t)(bm + r0) * K + c0 * 8;
    const size_t gb = (size_t)(bn + r0) * K + c0 * 8;
    const uint32_t sofs = (uint32_t)(r0 * RSTR + c0 * 16);

    const uint32_t a_part = (uint32_t)((wm * 32 + (lane & 15)) * RSTR + (lane >> 4) * 16);
    const uint32_t b_part = (uint32_t)((wn * 64 + (lane & 7) + ((lane >> 4) << 3)) * RSTR
                                       + ((lane >> 3) & 1) * 16);

    float acc[2][8][4];
#pragma unroll
    for (int i = 0; i < 2; i++)
#pragma unroll
        for (int j = 0; j < 8; j++)
#pragma unroll
            for (int q = 0; q < 4; q++) acc[i][j][q] = 0.f;

    {
        uint4 v0 = *(const uint4*)(Ah + ga);
        uint4 v1 = *(const uint4*)(Ah + ga + 64 * K);
        uint4 v2 = *(const uint4*)(Al + ga);
        uint4 v3 = *(const uint4*)(Al + ga + 64 * K);
        uint4 v4 = *(const uint4*)(Bh + gb);
        uint4 v5 = *(const uint4*)(Bh + gb + 64 * K);
        uint4 v6 = *(const uint4*)(Bl + gb);
        uint4 v7 = *(const uint4*)(Bl + gb + 64 * K);
        *(uint4*)(sal + 0 * TILE_B + sofs)             = v0;
        *(uint4*)(sal + 0 * TILE_B + sofs + 64 * RSTR) = v1;
        *(uint4*)(sal + 1 * TILE_B + sofs)             = v2;
        *(uint4*)(sal + 1 * TILE_B + sofs + 64 * RSTR) = v3;
        *(uint4*)(sal + 2 * TILE_B + sofs)             = v4;
        *(uint4*)(sal + 2 * TILE_B + sofs + 64 * RSTR) = v5;
        *(uint4*)(sal + 3 * TILE_B + sofs)             = v6;
        *(uint4*)(sal + 3 * TILE_B + sofs + 64 * RSTR) = v7;
    }
    __syncthreads();

    for (int c = 0; c < NC; c++) {
        const uint32_t so = (c & 1) ? STAGE_B : 0;
        uint4 v0, v1, v2, v3, v4, v5, v6, v7;
        const bool pre = (c + 1 < NC);
        if (pre) {
            const size_t k1 = (size_t)(c + 1) << 5;
            v0 = *(const uint4*)(Ah + ga + k1);
            v1 = *(const uint4*)(Ah + ga + k1 + 64 * K);
            v2 = *(const uint4*)(Al + ga + k1);
            v3 = *(const uint4*)(Al + ga + k1 + 64 * K);
            v4 = *(const uint4*)(Bh + gb + k1);
            v5 = *(const uint4*)(Bh + gb + k1 + 64 * K);
            v6 = *(const uint4*)(Bl + gb + k1);
            v7 = *(const uint4*)(Bl + gb + k1 + 64 * K);
        }

        const uint32_t sAh = sb + so + 0 * TILE_B;
        const uint32_t sAl = sb + so + 1 * TILE_B;
        const uint32_t sBh = sb + so + 2 * TILE_B;
        const uint32_t sBl = sb + so + 3 * TILE_B;

#pragma unroll
        for (int kk = 0; kk < 2; kk++) {
            uint32_t ah[2][4], al[2][4], bh[4][4], bl[4][4];
#pragma unroll
            for (int mt = 0; mt < 2; mt++) {
                ldmx4(ah[mt], sAh + a_part + mt * (16 * RSTR) + kk * 32);
                ldmx4(al[mt], sAl + a_part + mt * (16 * RSTR) + kk * 32);
            }
#pragma unroll
            for (int nt = 0; nt < 4; nt++) {
                ldmx4(bh[nt], sBh + b_part + nt * (16 * RSTR) + kk * 32);
                ldmx4(bl[nt], sBl + b_part + nt * (16 * RSTR) + kk * 32);
            }
#pragma unroll
            for (int mt = 0; mt < 2; mt++) {
#pragma unroll
                for (int nt = 0; nt < 4; nt++) {
                    mma16816(acc[mt][2 * nt],     ah[mt], bh[nt][0], bh[nt][1]);
                    mma16816(acc[mt][2 * nt],     ah[mt], bl[nt][0], bl[nt][1]);
                    mma16816(acc[mt][2 * nt],     al[mt], bh[nt][0], bh[nt][1]);
                    mma16816(acc[mt][2 * nt + 1], ah[mt], bh[nt][2], bh[nt][3]);
                    mma16816(acc[mt][2 * nt + 1], ah[mt], bl[nt][2], bl[nt][3]);
                    mma16816(acc[mt][2 * nt + 1], al[mt], bh[nt][2], bh[nt][3]);
                }
            }
        }

        if (pre) {
            const uint32_t so2 = so ^ STAGE_B;
            *(uint4*)(sal + so2 + 0 * TILE_B + sofs)             = v0;
            *(uint4*)(sal + so2 + 0 * TILE_B + sofs + 64 * RSTR) = v1;
            *(uint4*)(sal + so2 + 1 * TILE_B + sofs)             = v2;
            *(uint4*)(sal + so2 + 1 * TILE_B + sofs + 64 * RSTR) = v3;
            *(uint4*)(sal + so2 + 2 * TILE_B + sofs)             = v4;
            *(uint4*)(sal + so2 + 2 * TILE_B + sofs + 64 * RSTR) = v5;
            *(uint4*)(sal + so2 + 3 * TILE_B + sofs)             = v6;
            *(uint4*)(sal + so2 + 3 * TILE_B + sofs + 64 * RSTR) = v7;
        }
        __syncthreads();
    }

    const int mr = bm + wm * 32 + (lane >> 2);
    const int nc0 = bn + wn * 64 + (lane & 3) * 2;
#pragma unroll
    for (int mt = 0; mt < 2; mt++) {
#pragma unroll
        for (int n8 = 0; n8 < 8; n8++) {
            int row = mr + mt * 16;
            int col = nc0 + n8 * 8;
            *(float2*)(C + (size_t)row * N + col) =
                make_float2(acc[mt][n8][0], acc[mt][n8][1]);
            *(float2*)(C + (size_t)(row + 8) * N + col) =
                make_float2(acc[mt][n8][2], acc[mt][n8][3]);
        }
    }
}

// ---------------- RMSNorm + RoPE -> bf16 hi/lo; V split -----------------------
// grid (T, 32): 0..15 Q heads, 16..23 K heads, 24..31 V passthrough split
__global__ __launch_bounds__(128) void norm_rope_split(
    const float* __restrict__ qkv, const int* __restrict__ pos,
    const float* __restrict__ qw,  const float* __restrict__ kw,
    __nv_bfloat16* __restrict__ qh, __nv_bfloat16* __restrict__ ql,
    __nv_bfloat16* __restrict__ kh, __nv_bfloat16* __restrict__ kl,
    __nv_bfloat16* __restrict__ vh, __nv_bfloat16* __restrict__ vl)
{
    const int t  = blockIdx.x;
    const int hh = blockIdx.y;
    const int d  = threadIdx.x;

    if (hh >= NH + NKV) {   // V: split only
        int vhd = hh - (NH + NKV);
        size_t gsrc = (size_t)t * QKVN + QS + KVS + vhd * HD + d;
        size_t gdst = (size_t)t * KVS + vhd * HD + d;
        float x = qkv[gsrc];
        __nv_bfloat16 hx = __float2bfloat16_rn(x);
        vh[gdst] = hx;
        vl[gdst] = __float2bfloat16_rn(x - __bfloat162float(hx));
        return;
    }

    const float* src; const float* w;
    __nv_bfloat16* dsth; __nv_bfloat16* dstl; size_t dofs;
    if (hh < NH) {
        src = qkv + (size_t)t * QKVN + hh * HD;
        w = qw;
        dsth = qh; dstl = ql;
        dofs = ((size_t)t * NH + hh) * HD + d;
    } else {
        int khd = hh - NH;
        src = qkv + (size_t)t * QKVN + QS + khd * HD;
        w = kw;
        dsth = kh; dstl = kl;
        dofs = ((size_t)t * NKV + khd) * HD + d;
    }

    float x = src[d];
    float ss = x * x;
#pragma unroll
    for (int o = 16; o > 0; o >>= 1)
        ss += __shfl_xor_sync(0xffffffffu, ss, o);

    __shared__ float red[4];
    __shared__ float xs[128];
    if ((d & 31) == 0) red[d >> 5] = ss;
    __syncthreads();
    float ms = (red[0] + red[1] + red[2] + red[3]) * (1.f / 128.f);
    float xn = x * rsqrtf(ms + 1e-6f) * w[d];
    xs[d] = xn;
    __syncthreads();

    float p = (float)pos[t];
    int i = d & 63;
    float freq = p * exp2f((float)i * -0.2076205059304601f);
    float s, c;
    sincosf(freq, &s, &c);
    float other = (d < 64) ? xs[d + 64] : xs[d - 64];
    float val = (d < 64) ? (xn * c - other * s) : (xn * c + other * s);

    __nv_bfloat16 hv = __float2bfloat16_rn(val);
    dsth[dofs] = hv;
    dstl[dofs] = __float2bfloat16_rn(val - __bfloat162float(hv));
}

// ---------------- HMMA flash attention (bf16x3 QK^T and PV) -------------------
// Block: 128 q-rows x 1 head. 8 warps x 16 rows. KV tiles of 64.
#define ASTR 272                       // smem row stride bytes (136 bf16)
#define AT_K (64 * ASTR)               // 17408 per 64-row tile
#define ASMEM (4 * AT_K)               // 69632

__global__ __launch_bounds__(256, 1) void attn_mma(
    const __nv_bfloat16* __restrict__ Qh, const __nv_bfloat16* __restrict__ Ql,
    const __nv_bfloat16* __restrict__ Kh, const __nv_bfloat16* __restrict__ Kl,
    const __nv_bfloat16* __restrict__ Vh, const __nv_bfloat16* __restrict__ Vl,
    float* __restrict__ ctx)
{
    extern __shared__ char sm[];
    const int h   = blockIdx.y;
    const int kvh = h >> 1;
    const int q0  = (int)(gridDim.x - 1 - blockIdx.x) * 128;  // long blocks first
    const int tid = threadIdx.x;
    const int w   = tid >> 5;
    const int lane = tid & 31;
    const float scale = 0.088388347648318447f;

    const uint32_t sb = smem_u32(sm);

    // ---- stage Q (128 x 128 bf16, h & l), pull into A-fragments -------------
    {
        int row = tid >> 1, half = tid & 1;
        const size_t g = (size_t)(q0 + row) * QS + h * HD + half * 64;
        uint32_t so = (uint32_t)(row * ASTR + half * 128);
#pragma unroll
        for (int i = 0; i < 8; i++) {
            *(uint4*)(sm + so + i * 16)             = *(const uint4*)(Qh + g + i * 8);
            *(uint4*)(sm + 2 * AT_K + so + i * 16)  = *(const uint4*)(Ql + g + i * 8);
        }
    }
    __syncthreads();

    uint32_t qfh[8][4], qfl[8][4];
    const uint32_t apart = (uint32_t)((w * 16 + (lane & 15)) * ASTR + (lane >> 4) * 16);
#pragma unroll
    for (int kk = 0; kk < 8; kk++) {
        ldmx4(qfh[kk], sb + apart + kk * 32);
        ldmx4(qfl[kk], sb + 2 * AT_K + apart + kk * 32);
    }
    __syncthreads();   // done with Q staging; smem now K/V

    float oacc[16][4];
#pragma unroll
    for (int n = 0; n < 16; n++)
#pragma unroll
        for (int q = 0; q < 4; q++) oacc[n][q] = 0.f;
    float m0 = -INFINITY, m1 = -INFINITY, l0 = 0.f, l1 = 0.f;

    const uint32_t sKh = sb, sKl = sb + AT_K, sVh = sb + 2 * AT_K, sVl = sb + 3 * AT_K;
    const uint32_t bpart = (uint32_t)(((lane & 7) + ((lane >> 4) << 3)) * ASTR
                                      + ((lane >> 3) & 1) * 16);
    const uint32_t vpart = (uint32_t)((lane & 15) * ASTR + (lane >> 4) * 16);

    // loader task split: 64 rows x 2 halves x {K,V}
    const int lrow  = tid & 63;
    const int lhalf = (tid >> 6) & 1;
    const int lisv  = tid >> 7;
    char* ldH = sm + (lisv ? 2 * AT_K : 0);
    char* ldL = sm + (lisv ? 3 * AT_K : AT_K);

    const int ntile = (q0 >> 6) + 2;
    for (int t0 = 0; t0 < ntile; t0++) {
        const int s0 = t0 << 6;
        if (t0) __syncthreads();
        {
            const size_t g = (size_t)(s0 + lrow) * KVS + kvh * HD + lhalf * 64;
            const uint32_t so = (uint32_t)(lrow * ASTR + lhalf * 128);
            const __nv_bfloat16* srcH = lisv ? Vh : Kh;
            const __nv_bfloat16* srcL = lisv ? Vl : Kl;
#pragma unroll
            for (int i = 0; i < 8; i++) {
                *(uint4*)(ldH + so + i * 16) = *(const uint4*)(srcH + g + i * 8);
                *(uint4*)(ldL + so + i * 16) = *(const uint4*)(srcL + g + i * 8);
            }
        }
        __syncthreads();

        // ---- scores S[16,64] per warp (bf16x3) ------------------------------
        float sacc[8][4];
#pragma unroll
        for (int t = 0; t < 8; t++)
#pragma unroll
            for (int q = 0; q < 4; q++) sacc[t][q] = 0.f;

#pragma unroll
        for (int kk = 0; kk < 8; kk++) {
            uint32_t bh[4][4], bl[4][4];
#pragma unroll
            for (int nt = 0; nt < 4; nt++) {
                ldmx4(bh[nt], sKh + bpart + nt * (16 * ASTR) + kk * 32);
                ldmx4(bl[nt], sKl + bpart + nt * (16 * ASTR) + kk * 32);
            }
#pragma unroll
            for (int nt = 0; nt < 4; nt++) {
                mma16816(sacc[2 * nt],     qfh[kk], bh[nt][0], bh[nt][1]);
                mma16816(sacc[2 * nt],     qfh[kk], bl[nt][0], bl[nt][1]);
                mma16816(sacc[2 * nt],     qfl[kk], bh[nt][0], bh[nt][1]);
                mma16816(sacc[2 * nt + 1], qfh[kk], bh[nt][2], bh[nt][3]);
                mma16816(sacc[2 * nt + 1], qfh[kk], bl[nt][2], bl[nt][3]);
                mma16816(sacc[2 * nt + 1], qfl[kk], bh[nt][2], bh[nt][3]);
            }
        }

        // ---- online softmax ---------------------------------------------------
        const int qr0 = q0 + w * 16 + (lane >> 2);
        const int qr1 = qr0 + 8;
        const bool domask = (s0 + 63 > q0 + w * 16);
        float mt0 = -INFINITY, mt1 = -INFINITY;
#pragma unroll
        for (int t = 0; t < 8; t++) {
            int c = s0 + t * 8 + (lane & 3) * 2;
            float v0 = sacc[t][0] * scale, v1 = sacc[t][1] * scale;
            float v2 = sacc[t][2] * scale, v3 = sacc[t][3] * scale;
            if (domask) {
                if (c     > qr0) v0 = -1e30f;
                if (c + 1 > qr0) v1 = -1e30f;
                if (c     > qr1) v2 = -1e30f;
                if (c + 1 > qr1) v3 = -1e30f;
            }
            sacc[t][0] = v0; sacc[t][1] = v1; sacc[t][2] = v2; sacc[t][3] = v3;
            mt0 = fmaxf(mt0, fmaxf(v0, v1));
            mt1 = fmaxf(mt1, fmaxf(v2, v3));
        }
        mt0 = fmaxf(mt0, __shfl_xor_sync(0xffffffffu, mt0, 1));
        mt0 = fmaxf(mt0, __shfl_xor_sync(0xffffffffu, mt0, 2));
        mt1 = fmaxf(mt1, __shfl_xor_sync(0xffffffffu, mt1, 1));
        mt1 = fmaxf(mt1, __shfl_xor_sync(0xffffffffu, mt1, 2));
        float mn0 = fmaxf(m0, mt0), mn1 = fmaxf(m1, mt1);
        float f0 = __expf(m0 - mn0), f1 = __expf(m1 - mn1);
        m0 = mn0; m1 = mn1;

        float ls0 = 0.f, ls1 = 0.f;
#pragma unroll
        for (int t = 0; t < 8; t++) {
            sacc[t][0] = __expf(sacc[t][0] - mn0);
            sacc[t][1] = __expf(sacc[t][1] - mn0);
            sacc[t][2] = __expf(sacc[t][2] - mn1);
            sacc[t][3] = __expf(sacc[t][3] - mn1);
            ls0 += sacc[t][0] + sacc[t][1];
            ls1 += sacc[t][2] + sacc[t][3];
        }
        ls0 += __shfl_xor_sync(0xffffffffu, ls0, 1);
        ls0 += __shfl_xor_sync(0xffffffffu, ls0, 2);
        ls1 += __shfl_xor_sync(0xffffffffu, ls1, 1);
        ls1 += __shfl_xor_sync(0xffffffffu, ls1, 2);
        l0 = l0 * f0 + ls0;
        l1 = l1 * f1 + ls1;
#pragma unroll
        for (int n = 0; n < 16; n++) {
            oacc[n][0] *= f0; oacc[n][1] *= f0;
            oacc[n][2] *= f1; oacc[n][3] *= f1;
        }

        // ---- PV: in-register P frags (hi/lo), V via ldmatrix.trans ----------
#pragma unroll
        for (int ks = 0; ks < 4; ks++) {
            uint32_t pah[4], pal[4];
#pragma unroll
            for (int half = 0; half < 2; half++) {
                float x0 = sacc[2 * ks + half][0], x1 = sacc[2 * ks + half][1];
                float x2 = sacc[2 * ks + half][2], x3 = sacc[2 * ks + half][3];
                __nv_bfloat16 b0 = __float2bfloat16_rn(x0);
                __nv_bfloat16 b1 = __float2bfloat16_rn(x1);
                __nv_bfloat16 b2 = __float2bfloat16_rn(x2);
                __nv_bfloat16 b3 = __float2bfloat16_rn(x3);
                pah[2 * half]     = ((uint32_t)__bfloat16_as_ushort(b1) << 16)
                                    | __bfloat16_as_ushort(b0);
                pah[2 * half + 1] = ((uint32_t)__bfloat16_as_ushort(b3) << 16)
                                    | __bfloat16_as_ushort(b2);
                pal[2 * half]     = packbf(x0 - __bfloat162float(b0),
                                           x1 - __bfloat162float(b1));
                pal[2 * half + 1] = packbf(x2 - __bfloat162float(b2),
                                           x3 - __bfloat162float(b3));
            }
            // pah/pal order fix: A frag = {a0=(r0,k01), a1=(r1,k01), a2=(r0,k89), a3=(r1,k89)}
            uint32_t ah4[4] = {pah[0], pah[1], pah[2], pah[3]};
            uint32_t al4[4] = {pal[0], pal[1], pal[2], pal[3]};
#pragma unroll
            for (int nt = 0; nt < 8; nt++) {
                uint32_t vh4[4], vl4[4];
                ldmx4t(vh4, sVh + vpart + ks * (16 * ASTR) + nt * 32);
                ldmx4t(vl4, sVl + vpart + ks * (16 * ASTR) + nt * 32);
                mma16816(oacc[2 * nt],     ah4, vh4[0], vh4[1]);
                mma16816(oacc[2 * nt],     ah4, vl4[0], vl4[1]);
                mma16816(oacc[2 * nt],     al4, vh4[0], vh4[1]);
                mma16816(oacc[2 * nt + 1], ah4, vh4[2], vh4[3]);
                mma16816(oacc[2 * nt + 1], ah4, vl4[2], vl4[3]);
                mma16816(oacc[2 * nt + 1], al4, vh4[2], vh4[3]);
            }
        }
    }

    // ---- epilogue -------------------------------------------------------------
    float il0 = 1.f / l0, il1 = 1.f / l1;
    const int row0 = q0 + w * 16 + (lane >> 2);
#pragma unroll
    for (int n = 0; n < 16; n++) {
        int col = h * HD + n * 8 + (lane & 3) * 2;
        *(float2*)(ctx + (size_t)row0 * QS + col) =
            make_float2(oacc[n][0] * il0, oacc[n][1] * il0);
        *(float2*)(ctx + (size_t)(row0 + 8) * QS + col) =
            make_float2(oacc[n][2] * il1, oacc[n][3] * il1);
    }
}

// ============================================================
extern "C" void kernel_launch(void* const* d_in, const int* in_sizes, int n_in,
                              void* d_out, int out_size)
{
    const int*   positions = (const int*)d_in[0];
    const float* hidden    = (const float*)d_in[1];
    const float* qkv_w     = (const float*)d_in[2];
    const float* q_norm_w  = (const float*)d_in[3];
    const float* k_norm_w  = (const float*)d_in[4];
    const float* o_w       = (const float*)d_in[5];
    float* out = (float*)d_out;

    float *qkv, *ctx;
    cudaGetSymbolAddress((void**)&qkv, g_qkv);
    cudaGetSymbolAddress((void**)&ctx, g_ctx);
    __nv_bfloat16 *hid_h, *hid_l, *qw_h, *qw_l, *ow_h, *ow_l, *cx_h, *cx_l;
    __nv_bfloat16 *qh, *ql, *kh, *kl, *vh, *vl;
    cudaGetSymbolAddress((void**)&hid_h, g_hid_h);
    cudaGetSymbolAddress((void**)&hid_l, g_hid_l);
    cudaGetSymbolAddress((void**)&qw_h,  g_qkvw_h);
    cudaGetSymbolAddress((void**)&qw_l,  g_qkvw_l);
    cudaGetSymbolAddress((void**)&ow_h,  g_ow_h);
    cudaGetSymbolAddress((void**)&ow_l,  g_ow_l);
    cudaGetSymbolAddress((void**)&cx_h,  g_ctx_h);
    cudaGetSymbolAddress((void**)&cx_l,  g_ctx_l);
    cudaGetSymbolAddress((void**)&qh, g_qh);
    cudaGetSymbolAddress((void**)&ql, g_ql);
    cudaGetSymbolAddress((void**)&kh, g_kh);
    cudaGetSymbolAddress((void**)&kl, g_kl);
    cudaGetSymbolAddress((void**)&vh, g_vh);
    cudaGetSymbolAddress((void**)&vl, g_vl);

    cudaFuncSetAttribute(gemm_mma, cudaFuncAttributeMaxDynamicSharedMemorySize, DSMEM_B);
    cudaFuncSetAttribute(attn_mma, cudaFuncAttributeMaxDynamicSharedMemorySize, ASMEM);

    // 0) split fp32 operands into bf16 hi/lo
    split_bf16<<<(TT * HID / 4 + 255) / 256, 256>>>(hidden, hid_h, hid_l, TT * HID / 4);
    split_bf16<<<(QKVN * HID / 4 + 255) / 256, 256>>>(qkv_w, qw_h, qw_l, QKVN * HID / 4);
    split_bf16<<<(HID * QS / 4 + 255) / 256, 256>>>(o_w, ow_h, ow_l, HID * QS / 4);

    // 1) QKV projection (HMMA bf16x3)
    gemm_mma<<<dim3(QKVN / 128, TT / 128), 256, DSMEM_B>>>(
        hid_h, hid_l, qw_h, qw_l, qkv, TT, QKVN, HID);

    // 2) RMSNorm + RoPE -> bf16 splits; V split
    norm_rope_split<<<dim3(TT, NH + NKV + NKV), 128>>>(
        qkv, positions, q_norm_w, k_norm_w, qh, ql, kh, kl, vh, vl);

    // 3) causal GQA flash attention (HMMA bf16x3)
    attn_mma<<<dim3(TT / 128, NH), 256, ASMEM>>>(qh, ql, kh, kl, vh, vl, ctx);

    // 4) O projection (HMMA bf16x3)
    split_bf16<<<(TT * QS / 4 + 255) / 256, 256>>>(ctx, cx_h, cx_l, TT * QS / 4);
    gemm_mma<<<dim3(HID / 128, TT / 128), 256, DSMEM_B>>>(
        cx_h, cx_l, ow_h, ow_l, out, TT, HID, QS);
}